// round 1
// baseline (speedup 1.0000x reference)
#include <cuda_runtime.h>

#define C 80        // channels
#define S 9         // neighbors (seq len)
#define E 89        // C + S
#define F3 268      // 3*E=267 padded to 268
#define KP 92       // K dim 89 padded to 92
#define NB 8        // nodes per attn block
#define M_ROWS (NB*S)   // 72
#define NN_MAX 32768

__device__ float g_H[NN_MAX*C];
__device__ float g_U[NN_MAX*C];
__device__ float g_Wcat[4][KP*F3];   // [layer*2+head], transposed [k][f], Q|K|VO fused
__device__ float g_bcat[4][F3];
__device__ float g_bfo[4][E];
__device__ float g_stats[C+1];
__device__ float g_norm[C+1];

// ---------------- weight preprocessing: transpose + fuse Wvo = out_w * Wv ----
__global__ void k_pre(const float* __restrict__ qkv_w, const float* __restrict__ qkv_b,
                      const float* __restrict__ out_w, const float* __restrict__ out_b) {
    int lh = blockIdx.x;                 // layer*2 + head, 0..3
    const float* qw = qkv_w + lh*267*89;
    const float* qb = qkv_b + lh*267;
    const float* ow = out_w + lh*89*89;
    const float* ob = out_b + lh*89;
    int tid = threadIdx.x;
    // Wq, Wk transposed into cols 0..177
    for (int i = tid; i < 178*89; i += blockDim.x) {
        int f = i/89, k = i%89;
        g_Wcat[lh][k*F3 + f] = qw[i];
    }
    // Wvo[f][g] = sum_e out_w[f,e] * qkv_w[178+e, g]  -> cols 178..266
    for (int i = tid; i < 89*89; i += blockDim.x) {
        int f = i/89, g = i%89;
        float acc = 0.f;
        for (int e = 0; e < 89; e++) acc += ow[f*89+e]*qw[(178+e)*89+g];
        g_Wcat[lh][g*F3 + 178 + f] = acc;
    }
    // zero pads: column 267 (all k), rows k=89..91 (all f)
    for (int k = tid; k < KP; k += blockDim.x) g_Wcat[lh][k*F3 + 267] = 0.f;
    for (int i = tid; i < 3*F3; i += blockDim.x)
        g_Wcat[lh][(89 + i/F3)*F3 + (i%F3)] = 0.f;
    // biases: bcat (Q,K get qkv_b, VO gets 0); bfo = out_w @ bv + out_b
    for (int f = tid; f < F3; f += blockDim.x)
        g_bcat[lh][f] = (f < 178) ? qb[f] : 0.f;
    for (int f = tid; f < 89; f += blockDim.x) {
        float acc = ob[f];
        for (int e = 0; e < 89; e++) acc += qb[178+e]*ow[f*89+e];
        g_bfo[lh][f] = acc;
    }
}

// ---------------- h = x @ W1 ------------------------------------------------
__global__ void k_lin1(const float* __restrict__ x, const float* __restrict__ W1, int NN) {
    __shared__ float s_W[82*80];
    __shared__ float s_x[64*82];
    int tid = threadIdx.x;
    int n0 = blockIdx.x * 64;
    for (int i = tid; i < 82*80; i += blockDim.x) s_W[i] = W1[i];
    for (int i = tid; i < 64*82; i += blockDim.x) {
        int r = i/82; int n = n0 + r;
        s_x[i] = (n < NN) ? x[n*82 + i%82] : 0.f;
    }
    __syncthreads();
    for (int i = tid; i < 64*80; i += blockDim.x) {
        int r = i/80, c = i%80;
        float acc = 0.f;
        #pragma unroll 2
        for (int e = 0; e < 82; e++) acc += s_x[r*82+e]*s_W[e*80+c];
        int n = n0 + r;
        if (n < NN) g_H[n*80+c] = acc;
    }
}

// ---------------- v = relu(pairnorm(U));  h = v @ W2 ------------------------
__global__ void k_nlin2(const float* __restrict__ W2, int NN) {
    __shared__ float s_W[80*80];
    __shared__ float s_v[64*80];
    int tid = threadIdx.x;
    int n0 = blockIdx.x * 64;
    float inv = g_norm[80];
    for (int i = tid; i < 80*80; i += blockDim.x) s_W[i] = W2[i];
    for (int i = tid; i < 64*80; i += blockDim.x) {
        int r = i/80, c = i%80; int n = n0 + r;
        float v = 0.f;
        if (n < NN) v = fmaxf((g_U[n*80+c] - g_norm[c])*inv, 0.f);
        s_v[i] = v;
    }
    __syncthreads();
    for (int i = tid; i < 64*80; i += blockDim.x) {
        int r = i/80, c = i%80;
        float acc = 0.f;
        #pragma unroll 2
        for (int e = 0; e < 80; e++) acc += s_v[r*80+e]*s_W[e*80+c];
        int n = n0 + r;
        if (n < NN) g_H[n*80+c] = acc;
    }
}

// ---------------- fused attention block (the hot kernel) --------------------
// per block: NB=8 nodes.  z = [h[nbr] | I9] (72 x 92 padded),
// per head: QKV GEMM (72x268 = z @ Wcat_t) -> warp-per-node attention
// accumulate z + mha0 + mha1 into s_acc, then max over s + bias.
__global__ void k_attn(const int* __restrict__ nbr, const float* __restrict__ bpost,
                       int lhbase, int NN) {
    extern __shared__ float sm[];
    float* s_z   = sm;                       // [72][92]
    float* s_qkv = s_z + M_ROWS*KP;          // [72][268]
    float* s_acc = s_qkv + M_ROWS*F3;        // [8][9][80]
    float* s_p   = s_acc + NB*S*C;           // [8][9][12]
    __shared__ int s_src[M_ROWS];
    int tid = threadIdx.x;
    int node0 = blockIdx.x * NB;

    if (tid < M_ROWS) {
        int node = node0 + tid/S;
        s_src[tid] = (node < NN) ? nbr[node*S + (tid%S)] : 0;
    }
    __syncthreads();
    // build z cols 0..79 (+ copy into acc) and identity/pad cols 80..91
    for (int i = tid; i < M_ROWS*C; i += blockDim.x) {
        int m = i / C, e = i % C;
        float v = g_H[s_src[m]*C + e];
        s_z[m*KP + e] = v;
        s_acc[i] = v;
    }
    for (int i = tid; i < M_ROWS*12; i += blockDim.x) {
        int m = i / 12, j = i % 12;
        s_z[m*KP + C + j] = (j == (m % S)) ? 1.f : 0.f;
    }
    __syncthreads();

    int wid = tid >> 5, lane = tid & 31;
    const float scale = rsqrtf(89.0f);

    for (int h = 0; h < 2; h++) {
        int lh = lhbase + h;
        const float* __restrict__ W = g_Wcat[lh];
        const float* __restrict__ bc = g_bcat[lh];
        // GEMM: s_qkv[m][f] = sum_k s_z[m][k] * W[k][f] + bcat[f]
        for (int t = tid; t < 9*67; t += blockDim.x) {
            int mt = t / 67, nt = t % 67;
            int m0 = mt*8, f0 = nt*4;
            float acc[8][4];
            #pragma unroll
            for (int i = 0; i < 8; i++)
                #pragma unroll
                for (int j = 0; j < 4; j++) acc[i][j] = 0.f;
            #pragma unroll 2
            for (int kk = 0; kk < KP/4; kk++) {
                float4 wv0 = *reinterpret_cast<const float4*>(&W[(kk*4+0)*F3 + f0]);
                float4 wv1 = *reinterpret_cast<const float4*>(&W[(kk*4+1)*F3 + f0]);
                float4 wv2 = *reinterpret_cast<const float4*>(&W[(kk*4+2)*F3 + f0]);
                float4 wv3 = *reinterpret_cast<const float4*>(&W[(kk*4+3)*F3 + f0]);
                #pragma unroll
                for (int i = 0; i < 8; i++) {
                    float4 zv = *reinterpret_cast<const float4*>(&s_z[(m0+i)*KP + kk*4]);
                    acc[i][0] += zv.x*wv0.x + zv.y*wv1.x + zv.z*wv2.x + zv.w*wv3.x;
                    acc[i][1] += zv.x*wv0.y + zv.y*wv1.y + zv.z*wv2.y + zv.w*wv3.y;
                    acc[i][2] += zv.x*wv0.z + zv.y*wv1.z + zv.z*wv2.z + zv.w*wv3.z;
                    acc[i][3] += zv.x*wv0.w + zv.y*wv1.w + zv.z*wv2.w + zv.w*wv3.w;
                }
            }
            #pragma unroll
            for (int i = 0; i < 8; i++)
                #pragma unroll
                for (int j = 0; j < 4; j++)
                    s_qkv[(m0+i)*F3 + f0 + j] = acc[i][j] + bc[f0+j];
        }
        __syncthreads();

        // attention: one warp per node
        {
            int nl = wid;
            const float* Qb = s_qkv + (nl*S)*F3;
            for (int p = lane; p < 81; p += 32) {
                int s = p/9, t2 = p%9;
                const float* q = Qb + s*F3;
                const float* k = Qb + t2*F3 + E;
                float d = 0.f;
                #pragma unroll 4
                for (int e = 0; e < E; e++) d += q[e]*k[e];
                s_p[nl*108 + s*12 + t2] = d*scale;
            }
            __syncwarp();
            if (lane < 9) {
                float* row = s_p + nl*108 + lane*12;
                float mx = row[0];
                #pragma unroll
                for (int t2 = 1; t2 < 9; t2++) mx = fmaxf(mx, row[t2]);
                float ex[9]; float sum = 0.f;
                #pragma unroll
                for (int t2 = 0; t2 < 9; t2++) { ex[t2] = expf(row[t2]-mx); sum += ex[t2]; }
                float invs = 1.f/sum;
                #pragma unroll
                for (int t2 = 0; t2 < 9; t2++) row[t2] = ex[t2]*invs;
            }
            __syncwarp();
            const float* bfo = g_bfo[lh];
            for (int i = lane; i < S*C; i += 32) {
                int s = i / C, e = i % C;
                const float* pr = s_p + nl*108 + s*12;
                const float* vo = s_qkv + (nl*S)*F3 + 178 + e;
                float a = 0.f;
                #pragma unroll
                for (int t2 = 0; t2 < 9; t2++) a += pr[t2]*vo[t2*F3];
                s_acc[nl*S*C + i] += a + bfo[e];
            }
        }
        __syncthreads();
    }

    // max over s + post bias
    for (int i = tid; i < NB*C; i += blockDim.x) {
        int nl = i / C, e = i % C;
        int node = node0 + nl;
        if (node < NN) {
            float mx = s_acc[nl*S*C + e];
            #pragma unroll
            for (int s = 1; s < S; s++) mx = fmaxf(mx, s_acc[nl*S*C + s*C + e]);
            g_U[node*C + e] = mx + bpost[e];
        }
    }
}

// ---------------- pairnorm stats --------------------------------------------
__global__ void k_zero() { int t = threadIdx.x; if (t <= C) g_stats[t] = 0.f; }

__global__ void k_stats(int NN) {
    __shared__ float s_cs[C];
    __shared__ float s_ss[256];
    int tid = threadIdx.x;
    if (tid < C) s_cs[tid] = 0.f;
    __syncthreads();
    float ss = 0.f;
    if (tid < 240) {
        int c = tid % 80, g = tid / 80;
        int base = blockIdx.x * 128;
        float cs = 0.f;
        for (int r = g; r < 128; r += 3) {
            int n = base + r;
            if (n < NN) { float v = g_U[n*80+c]; cs += v; ss += v*v; }
        }
        atomicAdd(&s_cs[c], cs);
    }
    s_ss[tid] = ss;
    __syncthreads();
    if (tid == 0) {
        float t = 0.f;
        for (int i = 0; i < 256; i++) t += s_ss[i];
        atomicAdd(&g_stats[80], t);
    }
    if (tid < C) atomicAdd(&g_stats[tid], s_cs[tid]);
}

__global__ void k_fin(int NN) {
    if (threadIdx.x == 0) {
        float rN = 1.f / (float)NN;
        float s2 = 0.f;
        for (int c = 0; c < C; c++) {
            float mu = g_stats[c]*rN;
            g_norm[c] = mu;
            s2 += mu*mu;
        }
        g_norm[80] = rsqrtf(1e-5f + g_stats[80]*rN - s2);
    }
}

// ---------------- output ----------------------------------------------------
__global__ void k_out(const float* __restrict__ x, float* __restrict__ out, int NN) {
    float inv = g_norm[80];
    int idx = blockIdx.x*blockDim.x + threadIdx.x;
    int total = NN*80;
    for (; idx < total; idx += gridDim.x*blockDim.x) {
        int n = idx/80, c = idx%80;
        float u = fmaxf((g_U[idx] - g_norm[c])*inv, 0.f);
        float t = x[n*82+c] + u;
        if (c == 79 && (t > 1.f || t < -1.f)) t = 0.f;
        out[idx] = 0.5f*t;
    }
}

// ---------------- launcher --------------------------------------------------
extern "C" void kernel_launch(void* const* d_in, const int* in_sizes, int n_in,
                              void* d_out, int out_size) {
    const float* x      = (const float*)d_in[0];
    const float* W1     = (const float*)d_in[1];
    const float* b1     = (const float*)d_in[2];
    const float* W2     = (const float*)d_in[3];
    const float* b2     = (const float*)d_in[4];
    const float* qkv_w  = (const float*)d_in[5];
    const float* qkv_b  = (const float*)d_in[6];
    const float* out_w  = (const float*)d_in[7];
    const float* out_b  = (const float*)d_in[8];
    const int*   nbr    = (const int*)d_in[9];
    float* out = (float*)d_out;

    int NN = in_sizes[0] / 82;
    if (NN > NN_MAX) NN = NN_MAX;

    const int SMEM_ATTN = (M_ROWS*KP + M_ROWS*F3 + NB*S*C + NB*108) * 4; // 130176 B
    cudaFuncSetAttribute(k_attn, cudaFuncAttributeMaxDynamicSharedMemorySize, SMEM_ATTN);

    int gLin  = (NN + 63) / 64;
    int gAttn = (NN + NB - 1) / NB;
    int gStat = (NN + 127) / 128;

    k_pre<<<4, 256>>>(qkv_w, qkv_b, out_w, out_b);
    k_lin1<<<gLin, 256>>>(x, W1, NN);
    k_attn<<<gAttn, 256, SMEM_ATTN>>>(nbr, b1, 0, NN);
    k_zero<<<1, 128>>>();
    k_stats<<<gStat, 256>>>(NN);
    k_fin<<<1, 32>>>(NN);
    k_nlin2<<<gLin, 256>>>(W2, NN);
    k_attn<<<gAttn, 256, SMEM_ATTN>>>(nbr, b2, 2, NN);
    k_zero<<<1, 128>>>();
    k_stats<<<gStat, 256>>>(NN);
    k_fin<<<1, 32>>>(NN);
    k_out<<<256, 256>>>(x, out, NN);
}

// round 2
// speedup vs baseline: 1.3377x; 1.3377x over previous
#include <cuda_runtime.h>

#define C 80        // channels
#define S 9         // neighbors (seq len)
#define E 89        // C + S
#define KP 92       // K dim 89 padded to 92
#define F3P 280     // padded fused width: Q@0(92) | K@92(92) | VO@184(96)
#define QO 0
#define KO 92
#define VOO 184
#define NB 8        // nodes per attn block
#define M_ROWS (NB*S)   // 72
#define ATTN_THREADS 320
#define NN_MAX 32768

typedef unsigned long long ull;

__device__ __align__(16) float g_H[NN_MAX*C];
__device__ __align__(16) float g_U[NN_MAX*C];
__device__ __align__(16) float g_Wcat[4][KP*F3P];   // [layer*2+head], [k][f]
__device__ __align__(16) float g_bcat[4][F3P];
__device__ __align__(16) float g_bfo[4][92];
__device__ float g_statsA[81];
__device__ float g_statsB[81];

// ---------------- f32x2 helpers ---------------------------------------------
__device__ __forceinline__ void fma2(ull &d, ull a, ull b) {
    asm("fma.rn.f32x2 %0, %1, %2, %0;" : "+l"(d) : "l"(a), "l"(b));
}
__device__ __forceinline__ ull add2(ull a, ull b) {
    ull r; asm("add.rn.f32x2 %0, %1, %2;" : "=l"(r) : "l"(a), "l"(b)); return r;
}
__device__ __forceinline__ ull bcast2(float v) {
    ull r; asm("mov.b64 %0, {%1, %1};" : "=l"(r) : "f"(v)); return r;
}
__device__ __forceinline__ float hadd2(ull a) {
    float lo, hi; asm("mov.b64 {%0, %1}, %2;" : "=f"(lo), "=f"(hi) : "l"(a));
    return lo + hi;
}

// ---------------- weight preprocessing --------------------------------------
__global__ void k_pre(const float* __restrict__ qkv_w, const float* __restrict__ qkv_b,
                      const float* __restrict__ out_w, const float* __restrict__ out_b) {
    int lh = blockIdx.x;                 // layer*2 + head, 0..3
    const float* qw = qkv_w + lh*267*89;
    const float* qb = qkv_b + lh*267;
    const float* ow = out_w + lh*89*89;
    const float* ob = out_b + lh*89;
    int tid = threadIdx.x;

    if (blockIdx.x == 0) {
        for (int i = tid; i < 81; i += blockDim.x) { g_statsA[i] = 0.f; g_statsB[i] = 0.f; }
    }
    // zero init whole W + biases
    for (int i = tid; i < KP*F3P; i += blockDim.x) g_Wcat[lh][i] = 0.f;
    for (int i = tid; i < F3P; i += blockDim.x) g_bcat[lh][i] = 0.f;
    for (int i = tid; i < 92; i += blockDim.x) g_bfo[lh][i] = 0.f;
    __syncthreads();

    // Wq rows f=0..88 -> cols QO+f; Wk rows 89..177 -> cols KO+f
    for (int i = tid; i < 89*89; i += blockDim.x) {
        int f = i/89, k = i%89;
        g_Wcat[lh][k*F3P + QO + f] = qw[f*89 + k];
        g_Wcat[lh][k*F3P + KO + f] = qw[(89+f)*89 + k];
    }
    // Wvo[f][k] = sum_e out_w[f,e] * qkv_w[178+e, k]  -> cols VOO+f
    for (int i = tid; i < 89*89; i += blockDim.x) {
        int f = i/89, k = i%89;
        float acc = 0.f;
        for (int e = 0; e < 89; e++) acc += ow[f*89+e]*qw[(178+e)*89+k];
        g_Wcat[lh][k*F3P + VOO + f] = acc;
    }
    // biases
    for (int f = tid; f < 89; f += blockDim.x) {
        g_bcat[lh][QO + f] = qb[f];
        g_bcat[lh][KO + f] = qb[89+f];
        float acc = ob[f];
        for (int e = 0; e < 89; e++) acc += qb[178+e]*ow[f*89+e];
        g_bfo[lh][f] = acc;
    }
}

// ---------------- h = x @ W1 ------------------------------------------------
__global__ void k_lin1(const float* __restrict__ x, const float* __restrict__ W1, int NN) {
    __shared__ float s_W[82*80];
    __shared__ float s_x[64*82];
    int tid = threadIdx.x;
    int n0 = blockIdx.x * 64;
    for (int i = tid; i < 82*80; i += blockDim.x) s_W[i] = W1[i];
    for (int i = tid; i < 64*82; i += blockDim.x) {
        int r = i/82; int n = n0 + r;
        s_x[i] = (n < NN) ? x[n*82 + i%82] : 0.f;
    }
    __syncthreads();
    for (int i = tid; i < 64*80; i += blockDim.x) {
        int r = i/80, c = i%80;
        float acc = 0.f;
        #pragma unroll 2
        for (int e = 0; e < 82; e++) acc += s_x[r*82+e]*s_W[e*80+c];
        int n = n0 + r;
        if (n < NN) g_H[n*80+c] = acc;
    }
}

// ---------------- v = relu(pairnorm(U));  h = v @ W2 ------------------------
__global__ void k_nlin2(const float* __restrict__ W2, int NN) {
    __shared__ float s_W[80*80];
    __shared__ float s_v[64*80];
    __shared__ float s_mu[80];
    __shared__ float s_inv;
    int tid = threadIdx.x;
    int n0 = blockIdx.x * 64;
    float rN = 1.f/(float)NN;
    if (tid < 80) s_mu[tid] = g_statsA[tid]*rN;
    if (tid == 0) {
        float s2 = 0.f;
        for (int c2 = 0; c2 < 80; c2++) { float m = g_statsA[c2]*rN; s2 += m*m; }
        s_inv = rsqrtf(1e-5f + g_statsA[80]*rN - s2);
    }
    for (int i = tid; i < 80*80; i += blockDim.x) s_W[i] = W2[i];
    __syncthreads();
    float inv = s_inv;
    for (int i = tid; i < 64*80; i += blockDim.x) {
        int r = i/80, c = i%80; int n = n0 + r;
        float v = 0.f;
        if (n < NN) v = fmaxf((g_U[n*80+c] - s_mu[c])*inv, 0.f);
        s_v[i] = v;
    }
    __syncthreads();
    for (int i = tid; i < 64*80; i += blockDim.x) {
        int r = i/80, c = i%80;
        float acc = 0.f;
        #pragma unroll 2
        for (int e = 0; e < 80; e++) acc += s_v[r*80+e]*s_W[e*80+c];
        int n = n0 + r;
        if (n < NN) g_H[n*80+c] = acc;
    }
}

// ---------------- fused attention block (the hot kernel) --------------------
__global__ void __launch_bounds__(ATTN_THREADS, 1)
k_attn(const int* __restrict__ nbr, const float* __restrict__ bpost,
       int lhbase, int NN) {
    extern __shared__ float sm[];
    float* s_z   = sm;                       // [72][92]
    float* s_qkv = s_z + M_ROWS*KP;          // [72][280]
    float* s_acc = s_qkv + M_ROWS*F3P;       // [8][9][80]
    float* s_p   = s_acc + NB*S*C;           // [8][9][12]
    __shared__ int s_src[M_ROWS];
    int tid = threadIdx.x;
    int node0 = blockIdx.x * NB;

    if (tid < M_ROWS) {
        int node = node0 + tid/S;
        s_src[tid] = (node < NN) ? nbr[node*S + (tid%S)] : 0;
    }
    __syncthreads();
    // gather z cols 0..79 (float4) + copy into acc
    for (int i = tid; i < M_ROWS*20; i += ATTN_THREADS) {
        int m = i / 20, q4 = i % 20;
        float4 v = *reinterpret_cast<const float4*>(&g_H[s_src[m]*C + q4*4]);
        *reinterpret_cast<float4*>(&s_z[m*KP + q4*4]) = v;
        *reinterpret_cast<float4*>(&s_acc[m*C + q4*4]) = v;
    }
    // identity cols 80..88 + zero pads 89..91
    for (int i = tid; i < M_ROWS*12; i += ATTN_THREADS) {
        int m = i / 12, j = i % 12;
        s_z[m*KP + C + j] = (j == (m % S)) ? 1.f : 0.f;
    }
    __syncthreads();

    int wid = tid >> 5, lane = tid & 31;
    const float scale = rsqrtf(89.0f);

    for (int h = 0; h < 2; h++) {
        int lh = lhbase + h;
        const float* __restrict__ W = g_Wcat[lh];
        const float* __restrict__ bc = g_bcat[lh];

        // GEMM: s_qkv[m][f] = sum_k s_z[m][k] * W[k][f] + bcat[f]
        // 9 mtiles x 35 ftiles = 315 tiles, 8 rows x 8 cols (4 f32x2) each
        if (tid < 315) {
            int mt = tid / 35, ft = tid % 35;
            int m0 = mt*8, f0 = ft*8;
            ull acc[8][4];
            #pragma unroll
            for (int i = 0; i < 8; i++)
                #pragma unroll
                for (int j = 0; j < 4; j++) acc[i][j] = 0ull;
            const float* Wb = W + f0;
            #pragma unroll 2
            for (int k = 0; k < KP; k++) {
                ulonglong2 wA = *reinterpret_cast<const ulonglong2*>(Wb + (size_t)k*F3P);
                ulonglong2 wB = *reinterpret_cast<const ulonglong2*>(Wb + (size_t)k*F3P + 4);
                #pragma unroll
                for (int i = 0; i < 8; i++) {
                    ull zz = bcast2(s_z[(m0+i)*KP + k]);
                    fma2(acc[i][0], zz, wA.x);
                    fma2(acc[i][1], zz, wA.y);
                    fma2(acc[i][2], zz, wB.x);
                    fma2(acc[i][3], zz, wB.y);
                }
            }
            #pragma unroll
            for (int i = 0; i < 8; i++)
                #pragma unroll
                for (int j = 0; j < 4; j++) {
                    ull b = *reinterpret_cast<const ull*>(&bc[f0 + 2*j]);
                    *reinterpret_cast<ull*>(&s_qkv[(m0+i)*F3P + f0 + 2*j]) = add2(acc[i][j], b);
                }
        }
        __syncthreads();

        // attention: one warp per node (warps 0..7)
        if (wid < NB) {
            int nl = wid;
            // scores (f32x2 dots, pads are zero)
            for (int p = lane; p < 81; p += 32) {
                int s = p/9, t2 = p%9;
                const ull* q = reinterpret_cast<const ull*>(s_qkv + (nl*S+s)*F3P + QO);
                const ull* kk = reinterpret_cast<const ull*>(s_qkv + (nl*S+t2)*F3P + KO);
                ull a = 0ull;
                #pragma unroll
                for (int e = 0; e < 46; e++) fma2(a, q[e], kk[e]);
                s_p[nl*108 + s*12 + t2] = hadd2(a)*scale;
            }
            __syncwarp();
            if (lane < 9) {
                float* row = s_p + nl*108 + lane*12;
                float mx = row[0];
                #pragma unroll
                for (int t2 = 1; t2 < 9; t2++) mx = fmaxf(mx, row[t2]);
                float ex[9]; float sum = 0.f;
                #pragma unroll
                for (int t2 = 0; t2 < 9; t2++) { ex[t2] = expf(row[t2]-mx); sum += ex[t2]; }
                float invs = 1.f/sum;
                #pragma unroll
                for (int t2 = 0; t2 < 9; t2++) row[t2] = ex[t2]*invs;
            }
            __syncwarp();
            // PV: acc[s][e] += sum_t p[s][t] * vo[t][e] + bfo[e]   (f32x2 over e)
            {
                const float* pr = s_p + nl*108;
                float* accb = s_acc + nl*S*C;
                const float* vob = s_qkv + (nl*S)*F3P + VOO;
                const float* bfo = g_bfo[lh];
                #pragma unroll 1
                for (int s = 0; s < 9; s++) {
                    ull ps[9];
                    #pragma unroll
                    for (int t2 = 0; t2 < 9; t2++) ps[t2] = bcast2(pr[s*12 + t2]);
                    for (int ep = lane; ep < 40; ep += 32) {
                        ull a = *reinterpret_cast<const ull*>(&accb[s*C + ep*2]);
                        #pragma unroll
                        for (int t2 = 0; t2 < 9; t2++)
                            fma2(a, ps[t2], *reinterpret_cast<const ull*>(&vob[t2*F3P + ep*2]));
                        a = add2(a, *reinterpret_cast<const ull*>(&bfo[ep*2]));
                        *reinterpret_cast<ull*>(&accb[s*C + ep*2]) = a;
                    }
                }
            }
        }
        __syncthreads();
    }

    // max over s + post bias
    for (int i = tid; i < NB*C; i += ATTN_THREADS) {
        int nl = i / C, e = i % C;
        int node = node0 + nl;
        if (node < NN) {
            float mx = s_acc[nl*S*C + e];
            #pragma unroll
            for (int s = 1; s < S; s++) mx = fmaxf(mx, s_acc[nl*S*C + s*C + e]);
            g_U[node*C + e] = mx + bpost[e];
        }
    }
}

// ---------------- pairnorm stats --------------------------------------------
__global__ void k_stats(int NN, int which) {
    float* st = which ? g_statsB : g_statsA;
    __shared__ float s_cs[C];
    __shared__ float s_ss[256];
    int tid = threadIdx.x;
    if (tid < C) s_cs[tid] = 0.f;
    __syncthreads();
    float ss = 0.f;
    if (tid < 240) {
        int c = tid % 80, g = tid / 80;
        int base = blockIdx.x * 128;
        float cs = 0.f;
        for (int r = g; r < 128; r += 3) {
            int n = base + r;
            if (n < NN) { float v = g_U[n*80+c]; cs += v; ss += v*v; }
        }
        atomicAdd(&s_cs[c], cs);
    }
    s_ss[tid] = ss;
    __syncthreads();
    if (tid == 0) {
        float t = 0.f;
        for (int i = 0; i < 256; i++) t += s_ss[i];
        atomicAdd(&st[80], t);
    }
    if (tid < C) atomicAdd(&st[tid], s_cs[tid]);
}

// ---------------- output ----------------------------------------------------
__global__ void k_out(const float* __restrict__ x, float* __restrict__ out, int NN) {
    __shared__ float s_mu[80];
    __shared__ float s_inv;
    int tid = threadIdx.x;
    float rN = 1.f/(float)NN;
    if (tid < 80) s_mu[tid] = g_statsB[tid]*rN;
    if (tid == 0) {
        float s2 = 0.f;
        for (int c2 = 0; c2 < 80; c2++) { float m = g_statsB[c2]*rN; s2 += m*m; }
        s_inv = rsqrtf(1e-5f + g_statsB[80]*rN - s2);
    }
    __syncthreads();
    float inv = s_inv;
    int idx = blockIdx.x*blockDim.x + tid;
    int total = NN*80;
    for (; idx < total; idx += gridDim.x*blockDim.x) {
        int n = idx/80, c = idx%80;
        float u = fmaxf((g_U[idx] - s_mu[c])*inv, 0.f);
        float t = x[n*82+c] + u;
        if (c == 79 && (t > 1.f || t < -1.f)) t = 0.f;
        out[idx] = 0.5f*t;
    }
}

// ---------------- launcher --------------------------------------------------
extern "C" void kernel_launch(void* const* d_in, const int* in_sizes, int n_in,
                              void* d_out, int out_size) {
    const float* x      = (const float*)d_in[0];
    const float* W1     = (const float*)d_in[1];
    const float* b1     = (const float*)d_in[2];
    const float* W2     = (const float*)d_in[3];
    const float* b2     = (const float*)d_in[4];
    const float* qkv_w  = (const float*)d_in[5];
    const float* qkv_b  = (const float*)d_in[6];
    const float* out_w  = (const float*)d_in[7];
    const float* out_b  = (const float*)d_in[8];
    const int*   nbr    = (const int*)d_in[9];
    float* out = (float*)d_out;

    int NN = in_sizes[0] / 82;
    if (NN > NN_MAX) NN = NN_MAX;

    const int SMEM_ATTN = (M_ROWS*KP + M_ROWS*F3P + NB*S*C + NB*108) * 4; // 133632 B
    cudaFuncSetAttribute(k_attn, cudaFuncAttributeMaxDynamicSharedMemorySize, SMEM_ATTN);

    int gLin  = (NN + 63) / 64;
    int gAttn = (NN + NB - 1) / NB;
    int gStat = (NN + 127) / 128;

    k_pre<<<4, 256>>>(qkv_w, qkv_b, out_w, out_b);
    k_lin1<<<gLin, 256>>>(x, W1, NN);
    k_attn<<<gAttn, ATTN_THREADS, SMEM_ATTN>>>(nbr, b1, 0, NN);
    k_stats<<<gStat, 256>>>(NN, 0);
    k_nlin2<<<gLin, 256>>>(W2, NN);
    k_attn<<<gAttn, ATTN_THREADS, SMEM_ATTN>>>(nbr, b2, 2, NN);
    k_stats<<<gStat, 256>>>(NN, 1);
    k_out<<<256, 256>>>(x, out, NN);
}